// round 1
// baseline (speedup 1.0000x reference)
#include <cuda_runtime.h>

#define BATCH 64
#define CIN   384
#define COUT  384
#define NEXP  8
#define HW    784   // 28*28

// Scratch for per-sample aggregated weights: [b, o, i]  (37.75 MB)
__device__ float g_agg[BATCH * COUT * CIN];

// ---------------------------------------------------------------------------
// Kernel 1: agg[b,o,i] = sum_e rw[b,e] * w[e,o,i]
// Each thread owns one (o,i) pair: loads the 8 expert weights ONCE, then loops
// over all 64 batches. Weight tensor (4.7 MB) is read exactly once from HBM.
// ---------------------------------------------------------------------------
__global__ void agg_kernel(const float* __restrict__ rw,    // [B, E]
                           const float* __restrict__ w,     // [E, COUT, CIN]
                           float* __restrict__ agg)         // [B, COUT, CIN]
{
    __shared__ float s_rw[BATCH * NEXP];
    const int tid = threadIdx.x;
    for (int i = tid; i < BATCH * NEXP; i += blockDim.x) s_rw[i] = rw[i];
    __syncthreads();

    const int oi = blockIdx.x * blockDim.x + tid;
    if (oi >= COUT * CIN) return;

    float we[NEXP];
#pragma unroll
    for (int e = 0; e < NEXP; e++) we[e] = w[e * (COUT * CIN) + oi];

#pragma unroll 4
    for (int b = 0; b < BATCH; b++) {
        float acc = 0.f;
#pragma unroll
        for (int e = 0; e < NEXP; e++) acc = fmaf(s_rw[b * NEXP + e], we[e], acc);
        agg[b * (COUT * CIN) + oi] = acc;
    }
}

// ---------------------------------------------------------------------------
// Kernel 2: batched GEMM  out[b] (COUT x HW) = agg[b] (COUT x CIN) * x[b] (CIN x HW)
// BM=BN=64, BK=16, 256 threads, 4x4 register tile per thread.
// ---------------------------------------------------------------------------
#define BM 64
#define BN 64
#define BK 16

__global__ __launch_bounds__(256)
void gemm_kernel(const float* __restrict__ agg,   // [B, COUT, CIN]
                 const float* __restrict__ x,     // [B, CIN, HW]
                 float* __restrict__ out)         // [B, COUT, HW]
{
    const int b  = blockIdx.z;
    const int m0 = blockIdx.y * BM;   // output-channel tile
    const int n0 = blockIdx.x * BN;   // pixel tile

    const float* A  = agg + (size_t)b * COUT * CIN;  // row-major [COUT][CIN]
    const float* Xp = x   + (size_t)b * CIN  * HW;   // row-major [CIN][HW]
    float*       O  = out + (size_t)b * COUT * HW;

    __shared__ float As[BK][BM];   // A tile, transposed: [k][m]
    __shared__ float Xs[BK][BN];   // X tile: [k][n]

    const int tid = threadIdx.x;
    const int ty  = tid >> 4;      // 0..15  -> m sub-row
    const int tx  = tid & 15;      // 0..15  -> n sub-col

    // loader indices
    const int a_row  = tid >> 2;          // 0..63 (m within tile)
    const int a_col4 = (tid & 3) * 4;     // 0,4,8,12 (k)
    const int x_row  = tid >> 4;          // 0..15 (k within tile)
    const int x_col  = (tid & 15) * 4;    // 0..60 (n)

    float acc[4][4];
#pragma unroll
    for (int i = 0; i < 4; i++)
#pragma unroll
        for (int j = 0; j < 4; j++) acc[i][j] = 0.f;

    for (int k0 = 0; k0 < CIN; k0 += BK) {
        // Load A tile (64 m x 16 k), store transposed into As[k][m]
        {
            const float4 av = *reinterpret_cast<const float4*>(
                &A[(size_t)(m0 + a_row) * CIN + k0 + a_col4]);
            As[a_col4 + 0][a_row] = av.x;
            As[a_col4 + 1][a_row] = av.y;
            As[a_col4 + 2][a_row] = av.z;
            As[a_col4 + 3][a_row] = av.w;
        }
        // Load X tile (16 k x 64 n). HW=784 is a multiple of 16, and the tile
        // boundary (n0=768) leaves exactly 16 valid columns, so each float4 is
        // either fully valid or fully OOB.
        {
            const int n = n0 + x_col;
            float4 xv = make_float4(0.f, 0.f, 0.f, 0.f);
            if (n + 3 < HW)
                xv = *reinterpret_cast<const float4*>(
                    &Xp[(size_t)(k0 + x_row) * HW + n]);
            *reinterpret_cast<float4*>(&Xs[x_row][x_col]) = xv;
        }
        __syncthreads();

#pragma unroll
        for (int k = 0; k < BK; k++) {
            const float4 a  = *reinterpret_cast<const float4*>(&As[k][ty * 4]);
            const float4 xv = *reinterpret_cast<const float4*>(&Xs[k][tx * 4]);
            acc[0][0] = fmaf(a.x, xv.x, acc[0][0]);
            acc[0][1] = fmaf(a.x, xv.y, acc[0][1]);
            acc[0][2] = fmaf(a.x, xv.z, acc[0][2]);
            acc[0][3] = fmaf(a.x, xv.w, acc[0][3]);
            acc[1][0] = fmaf(a.y, xv.x, acc[1][0]);
            acc[1][1] = fmaf(a.y, xv.y, acc[1][1]);
            acc[1][2] = fmaf(a.y, xv.z, acc[1][2]);
            acc[1][3] = fmaf(a.y, xv.w, acc[1][3]);
            acc[2][0] = fmaf(a.z, xv.x, acc[2][0]);
            acc[2][1] = fmaf(a.z, xv.y, acc[2][1]);
            acc[2][2] = fmaf(a.z, xv.z, acc[2][2]);
            acc[2][3] = fmaf(a.z, xv.w, acc[2][3]);
            acc[3][0] = fmaf(a.w, xv.x, acc[3][0]);
            acc[3][1] = fmaf(a.w, xv.y, acc[3][1]);
            acc[3][2] = fmaf(a.w, xv.z, acc[3][2]);
            acc[3][3] = fmaf(a.w, xv.w, acc[3][3]);
        }
        __syncthreads();
    }

    // Write 4x4 output micro-tile
    const int nbase = n0 + tx * 4;
#pragma unroll
    for (int i = 0; i < 4; i++) {
        const int m = m0 + ty * 4 + i;
        if (nbase + 3 < HW) {
            float4 v = make_float4(acc[i][0], acc[i][1], acc[i][2], acc[i][3]);
            *reinterpret_cast<float4*>(&O[(size_t)m * HW + nbase]) = v;
        }
        // (nbase is a multiple of 4 and valid width at the edge tile is 16, so
        //  a float4 is either fully in range or fully out; no partial case.)
    }
}

extern "C" void kernel_launch(void* const* d_in, const int* in_sizes, int n_in,
                              void* d_out, int out_size)
{
    const float* x  = (const float*)d_in[0];   // [64, 384, 28, 28]
    const float* rw = (const float*)d_in[1];   // [64, 8]
    const float* w  = (const float*)d_in[2];   // [8, 384, 384]
    float* out = (float*)d_out;                // [64, 384, 28, 28]

    float* agg;
    cudaGetSymbolAddress((void**)&agg, g_agg);

    // Kernel 1: build per-sample weights
    {
        const int total = COUT * CIN;
        agg_kernel<<<(total + 255) / 256, 256>>>(rw, w, agg);
    }

    // Kernel 2: batched GEMM
    {
        dim3 grid((HW + BN - 1) / BN, COUT / BM, BATCH);  // 13 x 6 x 64
        gemm_kernel<<<grid, 256>>>(agg, x, out);
    }
}